// round 7
// baseline (speedup 1.0000x reference)
#include <cuda_runtime.h>
#include <cuda_fp16.h>

// BilateralSlice: grid (4,12,8,16,16) f32, guide (4,1,1024,1024) f32,
// out (4,12,1024,1024) f32.
//
// One CTA = (b, 4 rows). Per row, y-lerped fp16 z-pair slice:
//   S[r][x][z][c] = half2{ v_c(z), v_c(z+1) }
// Block-split pixel assignment: thread t covers x = t and x = t + 512, so
// every per-channel result is stored immediately with a fully-coalesced
// STG.32 (no 24-float accumulator transpose). Lean liveness -> 42-reg cap,
// 3 CTAs/SM (48 warps, 75% occupancy).

#define NB 4
#define NC 12
#define DG 8
#define HG 16
#define WG 16
#define HH 1024
#define WW 1024

constexpr int XSTRIDE = 100;             // words per x (96 + 4 pad)
constexpr int RSTRIDE = WG * XSTRIDE;    // 1600 words per row slice
constexpr int ROWS    = 4;
constexpr int THREADS = 512;

__global__ void __launch_bounds__(THREADS, 3)
bilateral_slice_kernel(const float* __restrict__ grid,
                       const float* __restrict__ guide,
                       float* __restrict__ out)
{
    __shared__ unsigned int S[ROWS * RSTRIDE];   // 6400 words = 25.6 KB

    const int b     = blockIdx.x >> 8;
    const int rg    = blockIdx.x & 255;
    const int ybase = rg * ROWS;
    const int tid   = threadIdx.x;

    // ---- stage y-lerped, z-paired fp16 slices for 4 rows ----
    const float* gb = grid + (size_t)b * (NC * DG * HG * WG);
    #pragma unroll
    for (int r = 0; r < ROWS; ++r) {
        const int   y   = ybase + r;
        const float iyf = (float)y * (15.0f / 1023.0f);
        const float y0f = floorf(iyf);
        const int   y0  = (int)y0f;
        const int   y1  = min(y0 + 1, HG - 1);
        const float fy  = iyf - y0f;
        const float wy0 = 1.0f - fy;

        #pragma unroll
        for (int i = tid; i < WG * DG * NC; i += THREADS) {
            int x  = i & 15;
            int zc = i >> 4;            // z*12 + c
            int z  = zc / 12;
            int c  = zc - z * 12;
            int zb = min(z + 1, DG - 1);
            const float* pz  = gb + (c * DG + z)  * (HG * WG);
            const float* pzb = gb + (c * DG + zb) * (HG * WG);
            float va = wy0 * pz[y0 * WG + x]  + fy * pz[y1 * WG + x];
            float vb = wy0 * pzb[y0 * WG + x] + fy * pzb[y1 * WG + x];
            __half2 h = __floats2half2_rn(va, vb);   // {v(z), v(z+1)}
            S[r * RSTRIDE + x * XSTRIDE + z * 12 + c] =
                *reinterpret_cast<unsigned int*>(&h);
        }
    }
    __syncthreads();

    // ---- x-dependent math for the 2 pixel slots (x = tid, x = tid+512) ----
    int     xA[2], xB[2];
    __half2 hwx0[2], hwx1[2];
    #pragma unroll
    for (int s = 0; s < 2; ++s) {
        const int   x    = tid + s * THREADS;
        const float ixf  = (float)x * (15.0f / 1023.0f);
        const float x0f  = floorf(ixf);
        const int   x0   = (int)x0f;
        const float fx   = ixf - x0f;
        xA[s]   = x0 * XSTRIDE;
        xB[s]   = min(x0 + 1, WG - 1) * XSTRIDE;
        hwx0[s] = __float2half2_rn(1.0f - fx);
        hwx1[s] = __float2half2_rn(fx);
    }

    const float* gpix = guide + (size_t)b * (HH * WW) + (size_t)ybase * WW;
    float*       obase = out + (size_t)b * NC * (size_t)(HH * WW)
                             + (size_t)ybase * WW;

    #pragma unroll
    for (int r = 0; r < ROWS; ++r) {
        // guide loads for both slots up front (coalesced LDG.32)
        float gv0 = __ldg(&gpix[(size_t)r * WW + tid]);
        float gv1 = __ldg(&gpix[(size_t)r * WW + tid + THREADS]);

        #pragma unroll
        for (int s = 0; s < 2; ++s) {
            const float gv = s ? gv1 : gv0;

            float iz  = __saturatef(gv) * (float)(DG - 1);
            float z0f = floorf(iz);
            int   z0  = (int)z0f;
            float fz  = iz - z0f;
            const float wz0 = 1.0f - fz;
            const float wz1 = fz;

            const int zo = r * RSTRIDE + z0 * 12;
            const uint4* pa = reinterpret_cast<const uint4*>(&S[xA[s] + zo]);
            const uint4* pb = reinterpret_cast<const uint4*>(&S[xB[s] + zo]);
            uint4 A0 = pa[0], A1 = pa[1], A2 = pa[2];
            uint4 B0 = pb[0], B1 = pb[1], B2 = pb[2];

            const unsigned int Aw[12] = {A0.x, A0.y, A0.z, A0.w,
                                         A1.x, A1.y, A1.z, A1.w,
                                         A2.x, A2.y, A2.z, A2.w};
            const unsigned int Bw[12] = {B0.x, B0.y, B0.z, B0.w,
                                         B1.x, B1.y, B1.z, B1.w,
                                         B2.x, B2.y, B2.z, B2.w};

            float* opix = obase + (size_t)r * WW + tid + s * THREADS;
            #pragma unroll
            for (int c = 0; c < NC; ++c) {
                __half2 a  = *reinterpret_cast<const __half2*>(&Aw[c]);
                __half2 bb = *reinterpret_cast<const __half2*>(&Bw[c]);
                __half2 t  = __hfma2(bb, hwx1[s], __hmul2(a, hwx0[s]));
                float2  f  = __half22float2(t);
                opix[(size_t)c * (HH * WW)] = fmaf(wz0, f.x, wz1 * f.y);
            }
        }
    }
}

extern "C" void kernel_launch(void* const* d_in, const int* in_sizes, int n_in,
                              void* d_out, int out_size)
{
    const float* grid  = nullptr;
    const float* guide = nullptr;
    for (int i = 0; i < n_in; ++i) {
        if (in_sizes[i] == NB * NC * DG * HG * WG) grid  = (const float*)d_in[i];
        else if (in_sizes[i] == NB * HH * WW)      guide = (const float*)d_in[i];
    }

    dim3 gridDim(NB * HH / ROWS);   // 1024 CTAs: one per (batch, 4-row group)
    bilateral_slice_kernel<<<gridDim, THREADS>>>(grid, guide, (float*)d_out);
}

// round 8
// speedup vs baseline: 1.0366x; 1.0366x over previous
#include <cuda_runtime.h>
#include <cuda_fp16.h>

// BilateralSlice: grid (4,12,8,16,16) f32, guide (4,1,1024,1024) f32,
// out (4,12,1024,1024) f32.
//
// One CTA = (b, 2 rows) -> 2048 CTAs (4.6 waves at 3 CTAs/SM: small tail).
// Per row, y-lerped fp16 z-pair slice in smem:
//   S[r][x][z][c] = half2{ v_c(z), v_c(z+1) }
// Block-split pixel assignment: thread t covers x = t and x = t + 512;
// per-channel results stored immediately as coalesced STG.32.
// Inner math identical to proven round-5/7 kernels.

#define NB 4
#define NC 12
#define DG 8
#define HG 16
#define WG 16
#define HH 1024
#define WW 1024

constexpr int XSTRIDE = 100;             // words per x (96 + 4 pad)
constexpr int RSTRIDE = WG * XSTRIDE;    // 1600 words per row slice
constexpr int ROWS    = 2;
constexpr int THREADS = 512;

__global__ void __launch_bounds__(THREADS, 3)
bilateral_slice_kernel(const float* __restrict__ grid,
                       const float* __restrict__ guide,
                       float* __restrict__ out)
{
    __shared__ unsigned int S[ROWS * RSTRIDE];   // 3200 words = 12.8 KB

    const int b     = blockIdx.x >> 9;
    const int rg    = blockIdx.x & 511;
    const int ybase = rg * ROWS;
    const int tid   = threadIdx.x;

    // ---- stage y-lerped, z-paired fp16 slices for 2 rows ----
    const float* gb = grid + (size_t)b * (NC * DG * HG * WG);
    #pragma unroll
    for (int r = 0; r < ROWS; ++r) {
        const int   y   = ybase + r;
        const float iyf = (float)y * (15.0f / 1023.0f);
        const float y0f = floorf(iyf);
        const int   y0  = (int)y0f;
        const int   y1  = min(y0 + 1, HG - 1);
        const float fy  = iyf - y0f;
        const float wy0 = 1.0f - fy;

        #pragma unroll
        for (int i = tid; i < WG * DG * NC; i += THREADS) {
            int x  = i & 15;
            int zc = i >> 4;            // z*12 + c
            int z  = zc / 12;
            int c  = zc - z * 12;
            int zb = min(z + 1, DG - 1);
            const float* pz  = gb + (c * DG + z)  * (HG * WG);
            const float* pzb = gb + (c * DG + zb) * (HG * WG);
            float va = wy0 * pz[y0 * WG + x]  + fy * pz[y1 * WG + x];
            float vb = wy0 * pzb[y0 * WG + x] + fy * pzb[y1 * WG + x];
            __half2 h = __floats2half2_rn(va, vb);   // {v(z), v(z+1)}
            S[r * RSTRIDE + x * XSTRIDE + z * 12 + c] =
                *reinterpret_cast<unsigned int*>(&h);
        }
    }
    __syncthreads();

    // ---- x-dependent math for the 2 pixel slots (x = tid, x = tid+512) ----
    int     xA[2], xB[2];
    __half2 hwx0[2], hwx1[2];
    #pragma unroll
    for (int s = 0; s < 2; ++s) {
        const int   x    = tid + s * THREADS;
        const float ixf  = (float)x * (15.0f / 1023.0f);
        const float x0f  = floorf(ixf);
        const int   x0   = (int)x0f;
        const float fx   = ixf - x0f;
        xA[s]   = x0 * XSTRIDE;
        xB[s]   = min(x0 + 1, WG - 1) * XSTRIDE;
        hwx0[s] = __float2half2_rn(1.0f - fx);
        hwx1[s] = __float2half2_rn(fx);
    }

    const float* gpix  = guide + (size_t)b * (HH * WW) + (size_t)ybase * WW;
    float*       obase = out + (size_t)b * NC * (size_t)(HH * WW)
                             + (size_t)ybase * WW;

    #pragma unroll
    for (int r = 0; r < ROWS; ++r) {
        float gv0 = __ldg(&gpix[(size_t)r * WW + tid]);
        float gv1 = __ldg(&gpix[(size_t)r * WW + tid + THREADS]);

        #pragma unroll
        for (int s = 0; s < 2; ++s) {
            const float gv = s ? gv1 : gv0;

            float iz  = __saturatef(gv) * (float)(DG - 1);
            float z0f = floorf(iz);
            int   z0  = (int)z0f;
            float fz  = iz - z0f;
            const float wz0 = 1.0f - fz;
            const float wz1 = fz;

            const int zo = r * RSTRIDE + z0 * 12;
            const uint4* pa = reinterpret_cast<const uint4*>(&S[xA[s] + zo]);
            const uint4* pb = reinterpret_cast<const uint4*>(&S[xB[s] + zo]);
            uint4 A0 = pa[0], A1 = pa[1], A2 = pa[2];
            uint4 B0 = pb[0], B1 = pb[1], B2 = pb[2];

            const unsigned int Aw[12] = {A0.x, A0.y, A0.z, A0.w,
                                         A1.x, A1.y, A1.z, A1.w,
                                         A2.x, A2.y, A2.z, A2.w};
            const unsigned int Bw[12] = {B0.x, B0.y, B0.z, B0.w,
                                         B1.x, B1.y, B1.z, B1.w,
                                         B2.x, B2.y, B2.z, B2.w};

            float* opix = obase + (size_t)r * WW + tid + s * THREADS;
            #pragma unroll
            for (int c = 0; c < NC; ++c) {
                __half2 a  = *reinterpret_cast<const __half2*>(&Aw[c]);
                __half2 bb = *reinterpret_cast<const __half2*>(&Bw[c]);
                __half2 t  = __hfma2(bb, hwx1[s], __hmul2(a, hwx0[s]));
                float2  f  = __half22float2(t);
                opix[(size_t)c * (HH * WW)] = fmaf(wz0, f.x, wz1 * f.y);
            }
        }
    }
}

extern "C" void kernel_launch(void* const* d_in, const int* in_sizes, int n_in,
                              void* d_out, int out_size)
{
    const float* grid  = nullptr;
    const float* guide = nullptr;
    for (int i = 0; i < n_in; ++i) {
        if (in_sizes[i] == NB * NC * DG * HG * WG) grid  = (const float*)d_in[i];
        else if (in_sizes[i] == NB * HH * WW)      guide = (const float*)d_in[i];
    }

    dim3 gridDim(NB * HH / ROWS);   // 2048 CTAs: one per (batch, 2-row group)
    bilateral_slice_kernel<<<gridDim, THREADS>>>(grid, guide, (float*)d_out);
}

// round 9
// speedup vs baseline: 1.1508x; 1.1102x over previous
#include <cuda_runtime.h>
#include <cuda_fp16.h>

// BilateralSlice: grid (4,12,8,16,16) f32, guide (4,1,1024,1024) f32,
// out (4,12,1024,1024) f32.
//
// DRAM-write-bound regime (201 MB fp32 output). R8 structure kept:
// one CTA = (b, 2 rows), y-lerped fp16 z-pair slice in smem,
// block-split pixels (x = t, t+512), coalesced STG.32 per channel.
// R9 deltas: guide prefetched before staging; streaming (__stcs) stores so
// output lines evict-first and the L2 write drain overlaps the kernel.

#define NB 4
#define NC 12
#define DG 8
#define HG 16
#define WG 16
#define HH 1024
#define WW 1024

constexpr int XSTRIDE = 100;             // words per x (96 + 4 pad)
constexpr int RSTRIDE = WG * XSTRIDE;    // 1600 words per row slice
constexpr int ROWS    = 2;
constexpr int THREADS = 512;

__global__ void __launch_bounds__(THREADS, 3)
bilateral_slice_kernel(const float* __restrict__ grid,
                       const float* __restrict__ guide,
                       float* __restrict__ out)
{
    __shared__ unsigned int S[ROWS * RSTRIDE];   // 3200 words = 12.8 KB

    const int b     = blockIdx.x >> 9;
    const int rg    = blockIdx.x & 511;
    const int ybase = rg * ROWS;
    const int tid   = threadIdx.x;

    // ---- prefetch guide for both rows/slots (overlaps staging latency) ----
    const float* gpix = guide + (size_t)b * (HH * WW) + (size_t)ybase * WW;
    float gvp[ROWS][2];
    #pragma unroll
    for (int r = 0; r < ROWS; ++r) {
        gvp[r][0] = __ldg(&gpix[(size_t)r * WW + tid]);
        gvp[r][1] = __ldg(&gpix[(size_t)r * WW + tid + THREADS]);
    }

    // ---- stage y-lerped, z-paired fp16 slices for 2 rows ----
    const float* gb = grid + (size_t)b * (NC * DG * HG * WG);
    #pragma unroll
    for (int r = 0; r < ROWS; ++r) {
        const int   y   = ybase + r;
        const float iyf = (float)y * (15.0f / 1023.0f);
        const float y0f = floorf(iyf);
        const int   y0  = (int)y0f;
        const int   y1  = min(y0 + 1, HG - 1);
        const float fy  = iyf - y0f;
        const float wy0 = 1.0f - fy;

        #pragma unroll
        for (int i = tid; i < WG * DG * NC; i += THREADS) {
            int x  = i & 15;
            int zc = i >> 4;            // z*12 + c
            int z  = zc / 12;
            int c  = zc - z * 12;
            int zb = min(z + 1, DG - 1);
            const float* pz  = gb + (c * DG + z)  * (HG * WG);
            const float* pzb = gb + (c * DG + zb) * (HG * WG);
            float va = wy0 * pz[y0 * WG + x]  + fy * pz[y1 * WG + x];
            float vb = wy0 * pzb[y0 * WG + x] + fy * pzb[y1 * WG + x];
            __half2 h = __floats2half2_rn(va, vb);   // {v(z), v(z+1)}
            S[r * RSTRIDE + x * XSTRIDE + z * 12 + c] =
                *reinterpret_cast<unsigned int*>(&h);
        }
    }
    __syncthreads();

    // ---- x-dependent math for the 2 pixel slots (x = tid, x = tid+512) ----
    int     xA[2], xB[2];
    __half2 hwx0[2], hwx1[2];
    #pragma unroll
    for (int s = 0; s < 2; ++s) {
        const int   x    = tid + s * THREADS;
        const float ixf  = (float)x * (15.0f / 1023.0f);
        const float x0f  = floorf(ixf);
        const int   x0   = (int)x0f;
        const float fx   = ixf - x0f;
        xA[s]   = x0 * XSTRIDE;
        xB[s]   = min(x0 + 1, WG - 1) * XSTRIDE;
        hwx0[s] = __float2half2_rn(1.0f - fx);
        hwx1[s] = __float2half2_rn(fx);
    }

    float* obase = out + (size_t)b * NC * (size_t)(HH * WW)
                       + (size_t)ybase * WW;

    #pragma unroll
    for (int r = 0; r < ROWS; ++r) {
        #pragma unroll
        for (int s = 0; s < 2; ++s) {
            const float gv = gvp[r][s];

            float iz  = __saturatef(gv) * (float)(DG - 1);
            float z0f = floorf(iz);
            int   z0  = (int)z0f;
            float fz  = iz - z0f;
            const float wz0 = 1.0f - fz;
            const float wz1 = fz;

            const int zo = r * RSTRIDE + z0 * 12;
            const uint4* pa = reinterpret_cast<const uint4*>(&S[xA[s] + zo]);
            const uint4* pb = reinterpret_cast<const uint4*>(&S[xB[s] + zo]);
            uint4 A0 = pa[0], A1 = pa[1], A2 = pa[2];
            uint4 B0 = pb[0], B1 = pb[1], B2 = pb[2];

            const unsigned int Aw[12] = {A0.x, A0.y, A0.z, A0.w,
                                         A1.x, A1.y, A1.z, A1.w,
                                         A2.x, A2.y, A2.z, A2.w};
            const unsigned int Bw[12] = {B0.x, B0.y, B0.z, B0.w,
                                         B1.x, B1.y, B1.z, B1.w,
                                         B2.x, B2.y, B2.z, B2.w};

            float* opix = obase + (size_t)r * WW + tid + s * THREADS;
            #pragma unroll
            for (int c = 0; c < NC; ++c) {
                __half2 a  = *reinterpret_cast<const __half2*>(&Aw[c]);
                __half2 bb = *reinterpret_cast<const __half2*>(&Bw[c]);
                __half2 t  = __hfma2(bb, hwx1[s], __hmul2(a, hwx0[s]));
                float2  f  = __half22float2(t);
                // streaming store: write-once data, evict-first
                __stcs(opix + (size_t)c * (HH * WW),
                       fmaf(wz0, f.x, wz1 * f.y));
            }
        }
    }
}

extern "C" void kernel_launch(void* const* d_in, const int* in_sizes, int n_in,
                              void* d_out, int out_size)
{
    const float* grid  = nullptr;
    const float* guide = nullptr;
    for (int i = 0; i < n_in; ++i) {
        if (in_sizes[i] == NB * NC * DG * HG * WG) grid  = (const float*)d_in[i];
        else if (in_sizes[i] == NB * HH * WW)      guide = (const float*)d_in[i];
    }

    dim3 gridDim(NB * HH / ROWS);   // 2048 CTAs: one per (batch, 2-row group)
    bilateral_slice_kernel<<<gridDim, THREADS>>>(grid, guide, (float*)d_out);
}

// round 10
// speedup vs baseline: 1.1985x; 1.0415x over previous
#include <cuda_runtime.h>
#include <cuda_fp16.h>

// BilateralSlice: grid (4,12,8,16,16) f32, guide (4,1,1024,1024) f32,
// out (4,12,1024,1024) f32.
//
// R9 structure (one CTA = (b, 2 rows); y-lerped fp16 z-pair smem slice;
// block-split pixels x = t, t+512; immediate __stcs STG.32 stores; guide
// prefetch) with R10 delta: 32-reg / 4-CTAs-per-SM occupancy push.
// Per-slot x-lerp params recomputed in-loop (no arrays) to keep liveness
// within the 32-reg budget without local-memory demotion.

#define NB 4
#define NC 12
#define DG 8
#define HG 16
#define WG 16
#define HH 1024
#define WW 1024

constexpr int XSTRIDE = 100;             // words per x (96 + 4 pad)
constexpr int RSTRIDE = WG * XSTRIDE;    // 1600 words per row slice
constexpr int ROWS    = 2;
constexpr int THREADS = 512;

__global__ void __launch_bounds__(THREADS, 4)
bilateral_slice_kernel(const float* __restrict__ grid,
                       const float* __restrict__ guide,
                       float* __restrict__ out)
{
    __shared__ unsigned int S[ROWS * RSTRIDE];   // 3200 words = 12.8 KB

    const int b     = blockIdx.x >> 9;
    const int rg    = blockIdx.x & 511;
    const int ybase = rg * ROWS;
    const int tid   = threadIdx.x;

    // ---- prefetch guide for both rows/slots (overlaps staging latency) ----
    const float* gpix = guide + (size_t)b * (HH * WW) + (size_t)ybase * WW;
    float gvp[ROWS][2];
    #pragma unroll
    for (int r = 0; r < ROWS; ++r) {
        gvp[r][0] = __ldg(&gpix[(size_t)r * WW + tid]);
        gvp[r][1] = __ldg(&gpix[(size_t)r * WW + tid + THREADS]);
    }

    // ---- stage y-lerped, z-paired fp16 slices for 2 rows ----
    const float* gb = grid + (size_t)b * (NC * DG * HG * WG);
    #pragma unroll
    for (int r = 0; r < ROWS; ++r) {
        const int   y   = ybase + r;
        const float iyf = (float)y * (15.0f / 1023.0f);
        const float y0f = floorf(iyf);
        const int   y0  = (int)y0f;
        const int   y1  = min(y0 + 1, HG - 1);
        const float fy  = iyf - y0f;
        const float wy0 = 1.0f - fy;

        #pragma unroll
        for (int i = tid; i < WG * DG * NC; i += THREADS) {
            int x  = i & 15;
            int zc = i >> 4;            // z*12 + c
            int z  = zc / 12;
            int c  = zc - z * 12;
            int zb = min(z + 1, DG - 1);
            const float* pz  = gb + (c * DG + z)  * (HG * WG);
            const float* pzb = gb + (c * DG + zb) * (HG * WG);
            float va = wy0 * pz[y0 * WG + x]  + fy * pz[y1 * WG + x];
            float vb = wy0 * pzb[y0 * WG + x] + fy * pzb[y1 * WG + x];
            __half2 h = __floats2half2_rn(va, vb);   // {v(z), v(z+1)}
            S[r * RSTRIDE + x * XSTRIDE + z * 12 + c] =
                *reinterpret_cast<unsigned int*>(&h);
        }
    }
    __syncthreads();

    float* obase = out + (size_t)b * NC * (size_t)(HH * WW)
                       + (size_t)ybase * WW;

    #pragma unroll
    for (int r = 0; r < ROWS; ++r) {
        #pragma unroll
        for (int s = 0; s < 2; ++s) {
            // ---- per-slot x-lerp params (recomputed: minimal liveness) ----
            const int   x    = tid + s * THREADS;
            const float ixf  = (float)x * (15.0f / 1023.0f);
            const float x0f  = floorf(ixf);
            const int   x0   = (int)x0f;
            const float fx   = ixf - x0f;
            const int   xa   = x0 * XSTRIDE;
            const int   xbv  = min(x0 + 1, WG - 1) * XSTRIDE;
            const __half2 hwx0 = __float2half2_rn(1.0f - fx);
            const __half2 hwx1 = __float2half2_rn(fx);

            const float gv = gvp[r][s];
            float iz  = __saturatef(gv) * (float)(DG - 1);
            float z0f = floorf(iz);
            int   z0  = (int)z0f;
            float fz  = iz - z0f;
            const float wz0 = 1.0f - fz;
            const float wz1 = fz;

            const int zo = r * RSTRIDE + z0 * 12;
            const uint4* pa = reinterpret_cast<const uint4*>(&S[xa + zo]);
            const uint4* pb = reinterpret_cast<const uint4*>(&S[xbv + zo]);
            uint4 A0 = pa[0], A1 = pa[1], A2 = pa[2];
            uint4 B0 = pb[0], B1 = pb[1], B2 = pb[2];

            const unsigned int Aw[12] = {A0.x, A0.y, A0.z, A0.w,
                                         A1.x, A1.y, A1.z, A1.w,
                                         A2.x, A2.y, A2.z, A2.w};
            const unsigned int Bw[12] = {B0.x, B0.y, B0.z, B0.w,
                                         B1.x, B1.y, B1.z, B1.w,
                                         B2.x, B2.y, B2.z, B2.w};

            float* opix = obase + (size_t)r * WW + x;
            #pragma unroll
            for (int c = 0; c < NC; ++c) {
                __half2 a  = *reinterpret_cast<const __half2*>(&Aw[c]);
                __half2 bb = *reinterpret_cast<const __half2*>(&Bw[c]);
                __half2 t  = __hfma2(bb, hwx1, __hmul2(a, hwx0));
                float2  f  = __half22float2(t);
                __stcs(opix + (size_t)c * (HH * WW),
                       fmaf(wz0, f.x, wz1 * f.y));
            }
        }
    }
}

extern "C" void kernel_launch(void* const* d_in, const int* in_sizes, int n_in,
                              void* d_out, int out_size)
{
    const float* grid  = nullptr;
    const float* guide = nullptr;
    for (int i = 0; i < n_in; ++i) {
        if (in_sizes[i] == NB * NC * DG * HG * WG) grid  = (const float*)d_in[i];
        else if (in_sizes[i] == NB * HH * WW)      guide = (const float*)d_in[i];
    }

    dim3 gridDim(NB * HH / ROWS);   // 2048 CTAs: one per (batch, 2-row group)
    bilateral_slice_kernel<<<gridDim, THREADS>>>(grid, guide, (float*)d_out);
}